// round 1
// baseline (speedup 1.0000x reference)
#include <cuda_runtime.h>

// Problem constants
#define BATCH 32
#define NN    2048
#define CC    8
#define FF    128
#define OO    128
#define K3    384          // 3 * FF
#define MT    64           // nodes per block (M tile)
#define KT    16           // K chunk staged in smem
#define NTHREADS 256

struct Smem {
    float As[K3 * MT];     // transposed X tile: As[k][m]   (96 KB)
    float Bs[KT * OO];     // W chunk: Bs[kk][o]             (8 KB)
    int   chs[MT * CC];    // child indices                  (2 KB)
    float crm[MT * CC];    // masked right coefficient       (2 KB)
    float clm[MT * CC];    // masked left coefficient        (2 KB)
};

__device__ __forceinline__ float4 f4zero() { float4 z; z.x=z.y=z.z=z.w=0.f; return z; }

__global__ void __launch_bounds__(NTHREADS, 2)
btconv_kernel(const float* __restrict__ nodes,
              const int*   __restrict__ children,
              const float* __restrict__ w_t,
              const float* __restrict__ w_l,
              const float* __restrict__ w_r,
              const float* __restrict__ bias,
              float*       __restrict__ out)
{
    extern __shared__ char smem_raw[];
    Smem& sm = *reinterpret_cast<Smem*>(smem_raw);

    const int tid = threadIdx.x;
    const int gn0 = blockIdx.x * MT;          // flattened (b*N + n) start; 64 | 2048 so no batch straddle
    const int b   = gn0 / NN;
    const int n0  = gn0 - b * NN;
    const float* __restrict__ nodesB = nodes + (size_t)b * NN * FF;

    // ---------------- phase 0: coefficients ----------------
    if (tid < MT) {
        const int m = tid;
        const int* chp = children + (size_t)(gn0 + m) * CC;
        int ch[CC];
        int ns = 0;
#pragma unroll
        for (int c = 0; c < CC; ++c) { ch[c] = chp[c]; ns += (ch[c] != 0); }
        const float nsf = (float)ns;
#pragma unroll
        for (int c = 0; c < CC; ++c) {
            const float mfl = (ch[c] != 0) ? 1.0f : 0.0f;
            float cr;
            if (ns == 1) {
                cr = (c == 0) ? 0.5f : 0.0f;
            } else {
                cr = ((float)c * mfl) / (nsf - 1.0f);   // ns==0: numerator 0 -> cr = -0
            }
            const float cl = (1.0f - cr) * mfl;
            sm.chs[m * CC + c] = ch[c];
            sm.crm[m * CC + c] = cr * mfl;   // fold mask so the gather is branchless
            sm.clm[m * CC + c] = cl;
        }
    }
    __syncthreads();

    // ---------------- phase 1: build transposed X tile ----------------
    {
        const int m  = tid & (MT - 1);        // node within tile
        const int fg = tid >> 6;              // 0..3 -> 32-float feature group
        const float* __restrict__ xrow = nodesB + (size_t)(n0 + m) * FF;

        int   ch[CC];
        float crv[CC], clv[CC];
#pragma unroll
        for (int c = 0; c < CC; ++c) {
            ch[c]  = sm.chs[m * CC + c];
            crv[c] = sm.crm[m * CC + c];
            clv[c] = sm.clm[m * CC + c];
        }

#pragma unroll
        for (int q = 0; q < 8; ++q) {
            const int f = fg * 32 + q * 4;
            const float4 xt = *reinterpret_cast<const float4*>(xrow + f);
            float4 r = f4zero(), l = f4zero();
#pragma unroll
            for (int c = 0; c < CC; ++c) {
                const float4 v = *reinterpret_cast<const float4*>(nodesB + (size_t)ch[c] * FF + f);
                r.x += crv[c] * v.x; r.y += crv[c] * v.y;
                r.z += crv[c] * v.z; r.w += crv[c] * v.w;
                l.x += clv[c] * v.x; l.y += clv[c] * v.y;
                l.z += clv[c] * v.z; l.w += clv[c] * v.w;
            }
            float* A0 = &sm.As[(f        ) * MT + m];
            float* A1 = &sm.As[(FF   + f ) * MT + m];
            float* A2 = &sm.As[(2*FF + f ) * MT + m];
            A0[0*MT] = xt.x; A0[1*MT] = xt.y; A0[2*MT] = xt.z; A0[3*MT] = xt.w;
            A1[0*MT] = r.x;  A1[1*MT] = r.y;  A1[2*MT] = r.z;  A1[3*MT] = r.w;
            A2[0*MT] = l.x;  A2[1*MT] = l.y;  A2[2*MT] = l.z;  A2[3*MT] = l.w;
        }
    }
    __syncthreads();

    // ---------------- phase 2: GEMM  C[64][128] = As^T @ W ----------------
    const int tx = tid & 15;          // -> 8 output columns: tx*8 .. tx*8+7
    const int ty = tid >> 4;          // -> 4 output rows:    ty*4 .. ty*4+3

    float acc[4][8];
#pragma unroll
    for (int i = 0; i < 4; ++i)
#pragma unroll
        for (int j = 0; j < 8; ++j) acc[i][j] = 0.f;

    for (int k0 = 0; k0 < K3; k0 += KT) {
        __syncthreads();              // protect previous Bs readers
        // stage KT x 128 rows of stacked W: [w_t ; w_r ; w_l]
#pragma unroll
        for (int i = 0; i < 2; ++i) {
            const int idx = tid + i * NTHREADS;     // float4 index, 0..511
            const int kk  = idx >> 5;               // row in tile
            const int o4  = idx & 31;               // float4 column
            const int k   = k0 + kk;
            const float* src = (k < FF)     ? (w_t + (size_t)k * OO)
                             : (k < 2*FF)   ? (w_r + (size_t)(k - FF) * OO)
                                            : (w_l + (size_t)(k - 2*FF) * OO);
            *reinterpret_cast<float4*>(&sm.Bs[kk * OO + o4 * 4]) =
                *reinterpret_cast<const float4*>(src + o4 * 4);
        }
        __syncthreads();

#pragma unroll
        for (int kk = 0; kk < KT; ++kk) {
            const int k = k0 + kk;
            const float4 a  = *reinterpret_cast<const float4*>(&sm.As[k * MT + ty * 4]);
            const float4 b0 = *reinterpret_cast<const float4*>(&sm.Bs[kk * OO + tx * 8]);
            const float4 b1 = *reinterpret_cast<const float4*>(&sm.Bs[kk * OO + tx * 8 + 4]);
            const float av[4] = {a.x, a.y, a.z, a.w};
            const float bv[8] = {b0.x, b0.y, b0.z, b0.w, b1.x, b1.y, b1.z, b1.w};
#pragma unroll
            for (int i = 0; i < 4; ++i)
#pragma unroll
                for (int j = 0; j < 8; ++j)
                    acc[i][j] += av[i] * bv[j];
        }
    }

    // ---------------- epilogue: bias + relu + store ----------------
    const float4 bb0 = *reinterpret_cast<const float4*>(bias + tx * 8);
    const float4 bb1 = *reinterpret_cast<const float4*>(bias + tx * 8 + 4);
    const float bv[8] = {bb0.x, bb0.y, bb0.z, bb0.w, bb1.x, bb1.y, bb1.z, bb1.w};

#pragma unroll
    for (int i = 0; i < 4; ++i) {
        const int m = ty * 4 + i;
        float* row = out + (size_t)(gn0 + m) * OO + tx * 8;
        float4 o0, o1;
        o0.x = fmaxf(acc[i][0] + bv[0], 0.f);
        o0.y = fmaxf(acc[i][1] + bv[1], 0.f);
        o0.z = fmaxf(acc[i][2] + bv[2], 0.f);
        o0.w = fmaxf(acc[i][3] + bv[3], 0.f);
        o1.x = fmaxf(acc[i][4] + bv[4], 0.f);
        o1.y = fmaxf(acc[i][5] + bv[5], 0.f);
        o1.z = fmaxf(acc[i][6] + bv[6], 0.f);
        o1.w = fmaxf(acc[i][7] + bv[7], 0.f);
        *reinterpret_cast<float4*>(row)     = o0;
        *reinterpret_cast<float4*>(row + 4) = o1;
    }
}

extern "C" void kernel_launch(void* const* d_in, const int* in_sizes, int n_in,
                              void* d_out, int out_size) {
    const float* nodes    = (const float*)d_in[0];   // [B,N,F]
    const int*   children = (const int*)  d_in[1];   // [B,N,C]
    const float* w_t      = (const float*)d_in[2];   // [F,O]
    const float* w_l      = (const float*)d_in[3];   // [F,O]
    const float* w_r      = (const float*)d_in[4];   // [F,O]
    const float* bias     = (const float*)d_in[5];   // [O]
    float* out = (float*)d_out;                      // [B,N,O]

    const int smem = (int)sizeof(Smem);              // ~110 KB
    cudaFuncSetAttribute(btconv_kernel, cudaFuncAttributeMaxDynamicSharedMemorySize, smem);

    const int grid = (BATCH * NN) / MT;              // 1024 blocks
    btconv_kernel<<<grid, NTHREADS, smem>>>(nodes, children, w_t, w_l, w_r, bias, out);
}